// round 16
// baseline (speedup 1.0000x reference)
#include <cuda_runtime.h>
#include <cstdint>

// VanillaRNN B=128,S=2048,E=256,H=512,V=128 fp32 — persistent kernel v12.
// CTAs 0..127: EXACT v6 recurrence skeleton with output projection REMOVED.
// CTAs 128..143: V-worker CTAs (2 per row-group) compute out[:,t,:] from
// h(t), pipelined 3+ steps behind the recurrence.
// Round-15 fixes vs failed v11:
//  - PER-ROW-GROUP vdone counters (the global counter let fast row-groups
//    pass the reuse guard on other groups' credit -> h overwrite race)
//  - V microtile rebuilt rec-style: 16 k-slices x (8x8) tiles, XOR-swizzled
//    Wfc, conflict-free LDS, 128 LDS.128/thread (was 256) -> V keeps pace.

#define Bb   128
#define Ss   2048
#define Vv   128
#define Ee   256
#define Hh   512
#define NBLK 144
#define NTHR 256

#define RR_STRIDE 516        // rec partials: Δbank 4 per slice row
#define VP_STRIDE 1028       // V partials: 257 units, odd mod 8

// ---- rec-CTA SMEM offsets (floats) ----
#define OFF_SH   0                       // h tile: 16 x 512
#define OFF_WH   8192                    // Wh slice: 512 k x 32 c (unit-XOR)
#define OFF_RR   24576                   // partials: 32 x 516 (end 41088)
// ---- V-CTA SMEM offsets (floats) ----
#define VWF      0                       // Wfc slice: 512 k x 64 c (unit-XOR)
#define VH       32768                   // h tile: 16 x 512
#define VPART    40960                   // partials: 16 x 1028 (end 57408)
#define SMEM_FLOATS 57408
#define SMEM_BYTES  (SMEM_FLOATS * 4)    // 229,632 B (< 227KB opt-in max)

__device__ float g_h[4][Bb * Hh];        // 4-deep h ring
__device__ float g_xw[Vv * Hh];          // token -> (emb@Wx + bx + bh)
__device__ int   g_bar8[8 * 32];         // per-row-group step counters
__device__ int   g_vd8[8 * 32];          // per-row-group V staging counters

static __device__ __forceinline__ float2 ffma2(float2 a, float2 b, float2 c) {
    union { float2 f; unsigned long long u; } A, B2, C;
    A.f = a; B2.f = b; C.f = c;
    asm("fma.rn.f32x2 %0, %1, %2, %0;" : "+l"(C.u) : "l"(A.u), "l"(B2.u));
    return C.f;
}

// g_xw[v][:] = emb[v] @ Wx + bx + bh ; also zeroes h(-1) and counters
__global__ void __launch_bounds__(512) xw_kernel(
    const float* __restrict__ emb, const float* __restrict__ Wx,
    const float* __restrict__ bx,  const float* __restrict__ bh)
{
    __shared__ float se[Ee];
    const int v = blockIdx.x, j = threadIdx.x;
    g_h[3][v * 512 + j] = 0.0f;          // h(-1) lives in ring slot 3
    if (v == 0 && j < 8 * 32) { g_bar8[j] = 0; g_vd8[j] = 0; }
    if (j < Ee) se[j] = emb[v * Ee + j];
    __syncthreads();
    float acc = 0.f;
#pragma unroll 8
    for (int e = 0; e < Ee; ++e) acc = fmaf(se[e], Wx[e * Hh + j], acc);
    g_xw[v * Hh + j] = acc + bx[j] + bh[j];
}

__global__ void __launch_bounds__(NTHR, 1)
rnn_persistent(const int*   __restrict__ x,
               const float* __restrict__ Wh,
               const float* __restrict__ Wfc,
               const float* __restrict__ bfc,
               float* __restrict__ out)
{
    extern __shared__ float sm[];
    const int tid  = threadIdx.x;
    const int bidx = blockIdx.x;

    uint32_t smem_u32;
    asm("{ .reg .u64 t0; cvta.to.shared.u64 t0, %1; cvt.u32.u64 %0, t0; }"
        : "=r"(smem_u32) : "l"(sm));

    if (bidx >= 128) {
        // ================= V-worker CTA =================
        const int vb  = bidx - 128;      // 0..15
        const int rv  = vb >> 1;         // row-group 0..7
        const int ch  = vb & 1;          // col half
        const int R0v = rv << 4;
        const int CV0 = ch << 6;         // 64 V-cols
        int* bar = &g_bar8[rv * 32];
        int* vd  = &g_vd8[rv * 32];
        // rec-style microtile: ksv = k-slice (32 k), tile = (rowg, colg) 8x8
        const int ksv   = tid & 15;
        const int tile  = tid >> 4;
        const int rowgv = tile >> 3;     // 0..1 -> rows rowgv*8..+7
        const int colgv = tile & 7;      // 0..7 -> cols colgv*8..+7
        const int hr0   = rowgv << 3;
        const int xv0 = (colgv * 2)     ^ (ksv & 7);
        const int xv1 = (colgv * 2 + 1) ^ (ksv & 7);
        const float4 bfv = *(const float4*)(bfc + CV0 + (tid & 15) * 4);

        // stage Wfc slice, unit-XOR swizzled (same scheme as rec's Wh)
        for (int idx = tid; idx < 512 * 64; idx += NTHR) {
            const int k = idx >> 6, c = idx & 63;
            const int u2 = (c >> 2) ^ ((k >> 2) & 7);
            sm[VWF + (k << 6) + u2 * 4 + (c & 3)] = Wfc[k * Vv + CV0 + c];
        }
        __syncthreads();
        const float4* wf4 = (const float4*)(sm + VWF);

        for (int t = 0; t < Ss; ++t) {
            if (tid == 0) {
                const int target = (t + 1) << 7;    // rec finished step t
                int v;
                do {
                    asm volatile("ld.acquire.gpu.global.b32 %0, [%1];"
                                 : "=r"(v) : "l"(bar) : "memory");
                } while (v - target < 0);
            }
            __syncthreads();
            // stage h(t) rows R0v..+15 from ring slot t&3
            const float* hs = g_h[t & 3];
#pragma unroll
            for (int jj = 0; jj < 8; ++jj) {
                const int idx = tid + (jj << 8);
                const int row = idx >> 7, u = idx & 127;
                const uint32_t sa = smem_u32 +
                    (uint32_t)((VH + (row << 9) + u * 4) * 4);
                asm volatile("cp.async.cg.shared.global [%0], [%1], 16;"
                    :: "r"(sa),
                       "l"(((const float4*)(hs + ((R0v + row) << 9))) + u));
            }
            asm volatile("cp.async.commit_group;");
            asm volatile("cp.async.wait_group 0;");
            __syncthreads();
            if (tid == 0)        // h(t) captured -> own row-group's credit
                asm volatile("red.release.gpu.global.add.s32 [%0], %1;"
                             :: "l"(vd), "r"(1) : "memory");

            float2 acc[32];
#pragma unroll
            for (int p = 0; p < 32; ++p) acc[p] = make_float2(0.f, 0.f);
#pragma unroll
            for (int m = 0; m < 8; ++m) {
                const int ub = (m << 4) + ksv;
                float4 h4[8];
#pragma unroll
                for (int r = 0; r < 8; ++r)
                    h4[r] = *(const float4*)(sm + VH
                              + ((hr0 + r) << 9) + ub * 4);
#pragma unroll
                for (int ki = 0; ki < 4; ++ki) {
                    const int k = (m << 6) + (ksv << 2) + ki;
                    const float4 wa = wf4[(k << 4) + xv0];
                    const float4 wb = wf4[(k << 4) + xv1];
#pragma unroll
                    for (int r = 0; r < 8; ++r) {
                        const float hv = ((const float*)&h4[r])[ki];
                        const float2 hh = make_float2(hv, hv);
                        acc[r*4+0] = ffma2(hh, make_float2(wa.x, wa.y), acc[r*4+0]);
                        acc[r*4+1] = ffma2(hh, make_float2(wa.z, wa.w), acc[r*4+1]);
                        acc[r*4+2] = ffma2(hh, make_float2(wb.x, wb.y), acc[r*4+2]);
                        acc[r*4+3] = ffma2(hh, make_float2(wb.z, wb.w), acc[r*4+3]);
                    }
                }
            }
            // partials: [ksv][row*64 + colgv*8]
#pragma unroll
            for (int r = 0; r < 8; ++r) {
                float* dst = sm + VPART + ksv * VP_STRIDE
                             + ((hr0 + r) << 6) + colgv * 8;
                *(float4*)dst       = make_float4(acc[r*4+0].x, acc[r*4+0].y,
                                                  acc[r*4+1].x, acc[r*4+1].y);
                *(float4*)(dst + 4) = make_float4(acc[r*4+2].x, acc[r*4+2].y,
                                                  acc[r*4+3].x, acc[r*4+3].y);
            }
            __syncthreads();
            // reduce 16 slices + bias, store one float4 of out
            {
                float4 s = bfv;
#pragma unroll
                for (int sl = 0; sl < 16; ++sl) {
                    const float4 v = *(const float4*)(sm + VPART
                                        + sl * VP_STRIDE + (tid << 2));
                    s.x += v.x; s.y += v.y; s.z += v.z; s.w += v.w;
                }
                const int row = tid >> 4;
                *(float4*)(out + (long)(R0v + row) * (Ss * Vv)
                           + (long)t * Vv + CV0 + (tid & 15) * 4) = s;
            }
            __syncthreads();
        }
        return;
    }

    // ================= recurrence CTA (exact v6 minus V) =================
    const int rgc  = bidx >> 4;          // row-group 0..7 (16 B-rows)
    const int R0   = rgc << 4;
    const int cg   = bidx & 15;
    const int C0   = cg << 5;            // 32 H-cols
    const int lane = tid & 31;
    const int ks   = lane;               // k-slice: k = m*128 + ks*4 + ki
    const int w    = tid >> 5;           // warp 0..7
    const int rowg = w >> 2;             // 0..1  -> rows rowg*8..+7
    const int colg = w & 3;              // 0..3  -> cols colg*8..+7
    const int hrow0 = rowg << 3;
    int* bar = &g_bar8[rgc * 32];
    int* vd  = &g_vd8[rgc * 32];
    const int x0u = (colg * 2)     ^ (ks & 7);
    const int x1u = (colg * 2 + 1) ^ (ks & 7);
    const int i2 = tid >> 4;             // 0..15
    const int j2 = (tid & 15) * 2;       // 0..30

    // ---- prologue: Wh slice (unit-XOR swizzle) -------------------------
    for (int idx = tid; idx < Hh * 32; idx += NTHR) {
        const int k = idx >> 5, c = idx & 31;
        const int u2 = (c >> 2) ^ ((k >> 2) & 7);
        sm[OFF_WH + (k << 5) + u2 * 4 + (c & 3)] = Wh[k * Hh + C0 + c];
    }
    __syncthreads();

    const float4* wh4 = (const float4*)(sm + OFF_WH);

    for (int t = 0; t < Ss; ++t) {
        // ---- per-warp lane0 acquire poll -------------------------------
        if (t > 0) {
            if (lane == 0) {
                const int target = t << 7;
                int v;
                do {
                    asm volatile("ld.acquire.gpu.global.b32 %0, [%1];"
                                 : "=r"(v) : "l"(bar) : "memory");
                } while (v - target < 0);
            }
            __syncwarp();
        }
        // ---- slot-reuse guard: OWN row-group's V staged h(t-4) ---------
        if (t >= 4 && tid == 0) {
            const int target = (t - 3) << 1;      // 2 V CTAs per row-group
            int v;
            do {
                asm volatile("ld.acquire.gpu.global.b32 %0, [%1];"
                             : "=r"(v) : "l"(vd) : "memory");
            } while (v - target < 0);
        }
        // ---- stage h(t-1): warp w stages rows 2w,2w+1; two k-halves ----
        const float* hsrc = g_h[(t + 3) & 3];
#pragma unroll
        for (int j = 0; j < 4; ++j) {            // half A: units 0..63
            const int idx = lane + (j << 5);
            const int row = 2 * w + (idx >> 6);
            const int u   = idx & 63;
            const uint32_t sa = smem_u32 +
                (uint32_t)((OFF_SH + (row << 9) + u * 4) * 4);
            asm volatile("cp.async.cg.shared.global [%0], [%1], 16;"
                :: "r"(sa), "l"(((const float4*)(hsrc + ((R0 + row) << 9))) + u));
        }
        asm volatile("cp.async.commit_group;");
#pragma unroll
        for (int j = 0; j < 4; ++j) {            // half B: units 64..127
            const int idx = lane + (j << 5);
            const int row = 2 * w + (idx >> 6);
            const int u   = 64 + (idx & 63);
            const uint32_t sa = smem_u32 +
                (uint32_t)((OFF_SH + (row << 9) + u * 4) * 4);
            asm volatile("cp.async.cg.shared.global [%0], [%1], 16;"
                :: "r"(sa), "l"(((const float4*)(hsrc + ((R0 + row) << 9))) + u));
        }
        asm volatile("cp.async.commit_group;");

        const int tk = __ldg(x + (R0 + i2) * Ss + t);

        asm volatile("cp.async.wait_group 1;");  // half A ready
        __syncthreads();

        const float2 xa = __ldg((const float2*)(g_xw + tk * Hh + C0 + j2));

        float2 accR[32];
#pragma unroll
        for (int p = 0; p < 32; ++p) accR[p] = make_float2(0.f, 0.f);

        // ---- compute m = 0,1 on k-half A -------------------------------
#pragma unroll
        for (int m = 0; m < 2; ++m) {
            const int ub = (m << 5) + ks;
            float4 h4[8];
#pragma unroll
            for (int r = 0; r < 8; ++r)
                h4[r] = *(const float4*)(sm + OFF_SH
                          + ((hrow0 + r) << 9) + ub * 4);
#pragma unroll
            for (int ki = 0; ki < 4; ++ki) {
                const int k = (m << 7) + (ks << 2) + ki;
                const float4 wa = wh4[(k << 3) + x0u];
                const float4 wb = wh4[(k << 3) + x1u];
#pragma unroll
                for (int r = 0; r < 8; ++r) {
                    const float hv = ((const float*)&h4[r])[ki];
                    const float2 hh = make_float2(hv, hv);
                    accR[r*4+0] = ffma2(hh, make_float2(wa.x, wa.y), accR[r*4+0]);
                    accR[r*4+1] = ffma2(hh, make_float2(wa.z, wa.w), accR[r*4+1]);
                    accR[r*4+2] = ffma2(hh, make_float2(wb.x, wb.y), accR[r*4+2]);
                    accR[r*4+3] = ffma2(hh, make_float2(wb.z, wb.w), accR[r*4+3]);
                }
            }
        }

        asm volatile("cp.async.wait_group 0;");  // half B ready
        __syncthreads();

        // ---- compute m = 2,3 on k-half B -------------------------------
#pragma unroll
        for (int m = 2; m < 4; ++m) {
            const int ub = (m << 5) + ks;
            float4 h4[8];
#pragma unroll
            for (int r = 0; r < 8; ++r)
                h4[r] = *(const float4*)(sm + OFF_SH
                          + ((hrow0 + r) << 9) + ub * 4);
#pragma unroll
            for (int ki = 0; ki < 4; ++ki) {
                const int k = (m << 7) + (ks << 2) + ki;
                const float4 wa = wh4[(k << 3) + x0u];
                const float4 wb = wh4[(k << 3) + x1u];
#pragma unroll
                for (int r = 0; r < 8; ++r) {
                    const float hv = ((const float*)&h4[r])[ki];
                    const float2 hh = make_float2(hv, hv);
                    accR[r*4+0] = ffma2(hh, make_float2(wa.x, wa.y), accR[r*4+0]);
                    accR[r*4+1] = ffma2(hh, make_float2(wa.z, wa.w), accR[r*4+1]);
                    accR[r*4+2] = ffma2(hh, make_float2(wb.x, wb.y), accR[r*4+2]);
                    accR[r*4+3] = ffma2(hh, make_float2(wb.z, wb.w), accR[r*4+3]);
                }
            }
        }
        // ---- write rec partials ---------------------------------------
#pragma unroll
        for (int r = 0; r < 8; ++r) {
            float* dst = sm + OFF_RR + ks * RR_STRIDE
                         + ((hrow0 + r) << 5) + colg * 8;
            *(float4*)dst       = make_float4(accR[r*4+0].x, accR[r*4+0].y,
                                              accR[r*4+1].x, accR[r*4+1].y);
            *(float4*)(dst + 4) = make_float4(accR[r*4+2].x, accR[r*4+2].y,
                                              accR[r*4+3].x, accR[r*4+3].y);
        }
        __syncthreads();
        // ---- reduce 32 slices, tanh, publish, per-warp release ---------
        {
            float2 s = xa;
#pragma unroll
            for (int sl = 0; sl < 32; ++sl) {
                const float2 v = *(const float2*)(sm + OFF_RR
                                    + sl * RR_STRIDE + tid * 2);
                s.x += v.x; s.y += v.y;
            }
            s.x = tanhf(s.x);
            s.y = tanhf(s.y);
            *(float2*)(&g_h[t & 3][((R0 + i2) << 9) + C0 + j2]) = s;
        }
        __syncwarp();
        if (lane == 0)
            asm volatile("red.release.gpu.global.add.s32 [%0], %1;"
                         :: "l"(bar), "r"(1) : "memory");
    }
}

extern "C" void kernel_launch(void* const* d_in, const int* in_sizes, int n_in,
                              void* d_out, int out_size) {
    const int*   x   = (const int*)  d_in[0];
    const float* emb = (const float*)d_in[1];
    const float* Wx  = (const float*)d_in[2];
    const float* bx  = (const float*)d_in[3];
    const float* Wh  = (const float*)d_in[4];
    const float* bh  = (const float*)d_in[5];
    const float* Wfc = (const float*)d_in[6];
    const float* bfc = (const float*)d_in[7];
    float* out = (float*)d_out;

    cudaFuncSetAttribute(rnn_persistent,
                         cudaFuncAttributeMaxDynamicSharedMemorySize, SMEM_BYTES);

    xw_kernel<<<Vv, 512>>>(emb, Wx, bx, bh);   // zeroes h(-1) + counters too
    rnn_persistent<<<NBLK, NTHR, SMEM_BYTES>>>(x, Wh, Wfc, bfc, out);
}